// round 3
// baseline (speedup 1.0000x reference)
#include <cuda_runtime.h>
#include <math.h>

#define D   128
#define NN  30000
#define NE  480000
#define NL  4
#define EPSV 1e-7f

// ---------------- device scratch (static, no allocation) ----------------
__device__ float g_h[NN * D];     // current node features
__device__ float g_out[NN * D];   // post-aggregation (agg + residual)
__device__ int   g_srcs[NE];      // CSR-ordered source node per edge
__device__ float g_attrs[NE];     // CSR-ordered edge attr scalar per edge
__device__ int   g_eids[NE];      // CSR-ordered original edge ids (for determinism sort)
__device__ int   g_row[NN + 1];   // CSR row offsets
__device__ int   g_cur[NN];       // histogram / scatter cursor

// ---------------- CSR build ----------------
__global__ void k_zero() {
    int i = blockIdx.x * blockDim.x + threadIdx.x;
    if (i < NN) g_cur[i] = 0;
}

__global__ void k_hist(const int* __restrict__ dst) {
    int e = blockIdx.x * blockDim.x + threadIdx.x;
    if (e < NE) atomicAdd(&g_cur[dst[e]], 1);
}

// single-block exclusive scan of g_cur -> g_row, also reset g_cur to row start (cursor)
__global__ void k_scan() {
    __shared__ int ssum[1024];
    int t = threadIdx.x;
    const int CH = (NN + 1023) / 1024;  // 30
    int base = t * CH;
    int s = 0;
    for (int i = 0; i < CH; i++) {
        int idx = base + i;
        if (idx < NN) s += g_cur[idx];
    }
    ssum[t] = s;
    __syncthreads();
    // Hillis-Steele inclusive scan over 1024 partials
    for (int off = 1; off < 1024; off <<= 1) {
        int v = (t >= off) ? ssum[t - off] : 0;
        __syncthreads();
        ssum[t] += v;
        __syncthreads();
    }
    int run = (t == 0) ? 0 : ssum[t - 1];  // exclusive prefix of this thread's chunk
    for (int i = 0; i < CH; i++) {
        int idx = base + i;
        if (idx < NN) {
            int c = g_cur[idx];
            g_row[idx] = run;
            g_cur[idx] = run;  // cursor for scatter
            run += c;
        }
    }
    if (t == 1023) g_row[NN] = run;  // == NE
}

__global__ void k_scatter(const int* __restrict__ src, const int* __restrict__ dst,
                          const float* __restrict__ attr) {
    int e = blockIdx.x * blockDim.x + threadIdx.x;
    if (e >= NE) return;
    int d = dst[e];
    int pos = atomicAdd(&g_cur[d], 1);
    g_eids[pos]  = e;
    g_srcs[pos]  = src[e];
    g_attrs[pos] = attr[e];
}

// per-node insertion sort by edge id -> deterministic reduction order
__global__ void k_sort() {
    int v = blockIdx.x * blockDim.x + threadIdx.x;
    if (v >= NN) return;
    int s = g_row[v], e = g_row[v + 1];
    for (int i = s + 1; i < e; i++) {
        int   key = g_eids[i];
        int   sr  = g_srcs[i];
        float at  = g_attrs[i];
        int j = i - 1;
        while (j >= s && g_eids[j] > key) {
            g_eids[j + 1]  = g_eids[j];
            g_srcs[j + 1]  = g_srcs[j];
            g_attrs[j + 1] = g_attrs[j];
            j--;
        }
        g_eids[j + 1]  = key;
        g_srcs[j + 1]  = sr;
        g_attrs[j + 1] = at;
    }
}

// ---------------- node encoder stage 1: h1 = relu(x @ Wn1 + bn1) ----------------
__global__ void k_enc1(const float* __restrict__ x, const float* __restrict__ Wn1,
                       const float* __restrict__ bn1) {
    int v = blockIdx.x;
    int c = threadIdx.x;
    __shared__ float sx[7];
    if (c < 7) sx[c] = x[v * 7 + c];
    __syncthreads();
    float acc = bn1[c];
#pragma unroll
    for (int k = 0; k < 7; k++) acc += sx[k] * Wn1[k * D + c];
    g_out[v * D + c] = fmaxf(acc, 0.f);
}

// ---------------- generic 128x128 Linear: C = A @ W + b  (A: [NN,128]) ----------------
#define TM 64
__global__ void k_gemm(const float* __restrict__ A, const float* __restrict__ W,
                       const float* __restrict__ b, float* __restrict__ C) {
    __shared__ float sW[32 * D];  // 16 KB: k-chunk of W, [32][128]
    __shared__ float sA[TM * 32]; // 8 KB: [64][32]
    int tid = threadIdx.x;  // 256
    int rowbase = blockIdx.x * TM;
    int tx = tid & 31;   // col group: cols tx*4 .. tx*4+3
    int ty = tid >> 5;   // row group: rows ty*8 .. ty*8+7

    float acc[8][4];
    float4 bb = ((const float4*)b)[tx];
#pragma unroll
    for (int i = 0; i < 8; i++) {
        acc[i][0] = bb.x; acc[i][1] = bb.y; acc[i][2] = bb.z; acc[i][3] = bb.w;
    }

    for (int kc = 0; kc < D; kc += 32) {
        // load W chunk: 32*128 floats = 1024 float4
        const float4* Wp = (const float4*)(W + kc * D);
        float4* sW4 = (float4*)sW;
        for (int i = tid; i < 1024; i += 256) sW4[i] = Wp[i];
        // load A chunk: 64 rows x 32 cols = 512 float4
        for (int i = tid; i < 512; i += 256) {
            int r = i >> 3, j = i & 7;
            int gr = rowbase + r;
            float4 vv = (gr < NN) ? ((const float4*)A)[gr * 32 + (kc >> 2) + j]
                                  : make_float4(0.f, 0.f, 0.f, 0.f);
            ((float4*)sA)[r * 8 + j] = vv;
        }
        __syncthreads();
#pragma unroll
        for (int k = 0; k < 32; k++) {
            float4 w = ((float4*)(sW + k * D))[tx];
#pragma unroll
            for (int i = 0; i < 8; i++) {
                float a = sA[(ty * 8 + i) * 32 + k];
                acc[i][0] += a * w.x;
                acc[i][1] += a * w.y;
                acc[i][2] += a * w.z;
                acc[i][3] += a * w.w;
            }
        }
        __syncthreads();
    }
#pragma unroll
    for (int i = 0; i < 8; i++) {
        int r = rowbase + ty * 8 + i;
        if (r < NN) {
            float4 o = make_float4(acc[i][0], acc[i][1], acc[i][2], acc[i][3]);
            ((float4*)C)[r * 32 + tx] = o;
        }
    }
}

// ---------------- GENConv aggregation: one block per node, one thread per channel ----
// online softmax over incoming edges: agg = sum(ex*msg)/sum(ex), out = agg + h
__global__ void k_agg(const float* __restrict__ We, const float* __restrict__ be) {
    int v = blockIdx.x;
    int c = threadIdx.x;
    int s = g_row[v], e = g_row[v + 1];
    float we_c = We[c], be_c = be[c];
    float m = -1e30f, den = 0.f, ws = 0.f;
    for (int i = s; i < e; i++) {
        int   sr = __ldg(&g_srcs[i]);
        float a  = __ldg(&g_attrs[i]);
        float hv = g_h[sr * D + c];
        float msg = fmaxf(hv + a * we_c + be_c, 0.f) + EPSV;
        // branchless online softmax update
        float newm  = fmaxf(m, msg);
        float scale = __expf(m - newm);   // 1 when m unchanged
        float ex    = __expf(msg - newm); // <= 1
        den = den * scale + ex;
        ws  = ws  * scale + ex * msg;
        m = newm;
    }
    float hvv = g_h[v * D + c];
    float agg = (e > s) ? (ws / den) : 0.f;
    g_out[v * D + c] = agg + hvv;
}

// ---------------- output head: out = h @ Wo + bo, one warp per node ----------------
__global__ void k_head(const float* __restrict__ Wo, const float* __restrict__ bo,
                       float* __restrict__ out) {
    int gw   = (blockIdx.x * blockDim.x + threadIdx.x) >> 5;
    int lane = threadIdx.x & 31;
    if (gw >= NN) return;
    float h0 = g_h[gw * D + lane];
    float h1 = g_h[gw * D + lane + 32];
    float h2 = g_h[gw * D + lane + 64];
    float h3 = g_h[gw * D + lane + 96];
#pragma unroll
    for (int o = 0; o < 3; o++) {
        float acc = h0 * __ldg(&Wo[lane * 3 + o]) + h1 * __ldg(&Wo[(lane + 32) * 3 + o]) +
                    h2 * __ldg(&Wo[(lane + 64) * 3 + o]) + h3 * __ldg(&Wo[(lane + 96) * 3 + o]);
#pragma unroll
        for (int off = 16; off; off >>= 1) acc += __shfl_down_sync(0xffffffff, acc, off);
        if (lane == 0) out[gw * 3 + o] = acc + bo[o];
    }
}

// ---------------- launch ----------------
extern "C" void kernel_launch(void* const* d_in, const int* in_sizes, int n_in,
                              void* d_out, int out_size) {
    const float* x    = (const float*)d_in[0];
    const int*   ei   = (const int*)d_in[1];   // [2, NE]
    const float* attr = (const float*)d_in[2];
    const float* Wn1  = (const float*)d_in[3];
    const float* bn1  = (const float*)d_in[4];
    const float* Wn2  = (const float*)d_in[5];
    const float* bn2  = (const float*)d_in[6];
    const float* We   = (const float*)d_in[7];
    const float* be   = (const float*)d_in[8];
    const float* Wg   = (const float*)d_in[9];  // [4,128,128]
    const float* bg   = (const float*)d_in[10]; // [4,128]
    const float* Wo   = (const float*)d_in[11];
    const float* bo   = (const float*)d_in[12];
    float* out = (float*)d_out;

    const int* src = ei;
    const int* dst = ei + NE;

    // device-global pointers for the GEMM: resolve g_h / g_out addresses
    float* p_h;
    float* p_out;
    cudaGetSymbolAddress((void**)&p_h, g_h);
    cudaGetSymbolAddress((void**)&p_out, g_out);

    // ---- CSR build (deterministic after per-node sort) ----
    k_zero<<<(NN + 255) / 256, 256>>>();
    k_hist<<<(NE + 255) / 256, 256>>>(dst);
    k_scan<<<1, 1024>>>();
    k_scatter<<<(NE + 255) / 256, 256>>>(src, dst, attr);
    k_sort<<<(NN + 255) / 256, 256>>>();

    // ---- node encoder ----
    k_enc1<<<NN, D>>>(x, Wn1, bn1);                 // g_out = relu(x@Wn1+bn1)
    int gblocks = (NN + TM - 1) / TM;
    k_gemm<<<gblocks, 256>>>(p_out, Wn2, bn2, p_h); // g_h = g_out@Wn2+bn2

    // ---- 4 GENConv layers ----
    for (int l = 0; l < NL; l++) {
        k_agg<<<NN, D>>>(We, be);                                  // g_out = agg + g_h
        k_gemm<<<gblocks, 256>>>(p_out, Wg + l * D * D, bg + l * D, p_h); // g_h = g_out@Wg+bg
    }

    // ---- head ----
    k_head<<<(NN * 32 + 255) / 256, 256>>>(Wo, bo, out);
}

// round 4
// speedup vs baseline: 1.0299x; 1.0299x over previous
#include <cuda_runtime.h>
#include <math.h>
#include <stdint.h>

#define D   128
#define NN  30000
#define NE  480000
#define NL  4
#define EPSV 1e-7f

// ---------------- device scratch (static, no allocation) ----------------
__device__ float g_h[NN * D];     // current node features
__device__ float g_out[NN * D];   // post-aggregation (agg + residual)
__device__ int   g_srcs[NE];      // CSR-ordered source node per edge
__device__ float g_attrs[NE];     // CSR-ordered edge attr scalar per edge
__device__ int   g_eids[NE];      // CSR-ordered original edge ids (determinism sort key)
__device__ int   g_row[NN + 1];   // CSR row offsets
__device__ int   g_cur[NN];       // histogram / scatter cursor

// ---------------- CSR build ----------------
__global__ void k_zero() {
    int i = blockIdx.x * blockDim.x + threadIdx.x;
    if (i < NN) g_cur[i] = 0;
}

__global__ void k_hist(const int* __restrict__ dst) {
    int e = blockIdx.x * blockDim.x + threadIdx.x;
    if (e < NE) atomicAdd(&g_cur[dst[e]], 1);
}

// single-block exclusive scan of g_cur -> g_row, also reset g_cur to row start (cursor)
__global__ void k_scan() {
    __shared__ int ssum[1024];
    int t = threadIdx.x;
    const int CH = (NN + 1023) / 1024;  // 30
    int base = t * CH;
    int s = 0;
    for (int i = 0; i < CH; i++) {
        int idx = base + i;
        if (idx < NN) s += g_cur[idx];
    }
    ssum[t] = s;
    __syncthreads();
    for (int off = 1; off < 1024; off <<= 1) {
        int v = (t >= off) ? ssum[t - off] : 0;
        __syncthreads();
        ssum[t] += v;
        __syncthreads();
    }
    int run = (t == 0) ? 0 : ssum[t - 1];
    for (int i = 0; i < CH; i++) {
        int idx = base + i;
        if (idx < NN) {
            int c = g_cur[idx];
            g_row[idx] = run;
            g_cur[idx] = run;
            run += c;
        }
    }
    if (t == 1023) g_row[NN] = run;
}

__global__ void k_scatter(const int* __restrict__ src, const int* __restrict__ dst,
                          const float* __restrict__ attr) {
    int e = blockIdx.x * blockDim.x + threadIdx.x;
    if (e >= NE) return;
    int d = dst[e];
    int pos = atomicAdd(&g_cur[d], 1);
    g_eids[pos]  = e;
    g_srcs[pos]  = src[e];
    g_attrs[pos] = attr[e];
}

// per-node insertion sort by edge id -> deterministic reduction order
__global__ void k_sort() {
    int v = blockIdx.x * blockDim.x + threadIdx.x;
    if (v >= NN) return;
    int s = g_row[v], e = g_row[v + 1];
    for (int i = s + 1; i < e; i++) {
        int   key = g_eids[i];
        int   sr  = g_srcs[i];
        float at  = g_attrs[i];
        int j = i - 1;
        while (j >= s && g_eids[j] > key) {
            g_eids[j + 1]  = g_eids[j];
            g_srcs[j + 1]  = g_srcs[j];
            g_attrs[j + 1] = g_attrs[j];
            j--;
        }
        g_eids[j + 1]  = key;
        g_srcs[j + 1]  = sr;
        g_attrs[j + 1] = at;
    }
}

// ---------------- node encoder stage 1: h1 = relu(x @ Wn1 + bn1) ----------------
__global__ void k_enc1(const float* __restrict__ x, const float* __restrict__ Wn1,
                       const float* __restrict__ bn1) {
    int v = blockIdx.x;
    int c = threadIdx.x;
    __shared__ float sx[7];
    if (c < 7) sx[c] = x[v * 7 + c];
    __syncthreads();
    float acc = bn1[c];
#pragma unroll
    for (int k = 0; k < 7; k++) acc += sx[k] * Wn1[k * D + c];
    g_out[v * D + c] = fmaxf(acc, 0.f);
}

// ---------------- tensor-core 128x128 Linear (3xTF32): C = A @ W + b ----------------
__device__ __forceinline__ uint32_t f2tf32(float x) {
    uint32_t r;
    asm("cvt.rna.tf32.f32 %0, %1;" : "=r"(r) : "f"(x));
    return r;
}
__device__ __forceinline__ void mma_tf32(float* c, const uint32_t* a, const uint32_t* b) {
    asm volatile(
        "mma.sync.aligned.m16n8k8.row.col.f32.tf32.tf32.f32 "
        "{%0,%1,%2,%3}, {%4,%5,%6,%7}, {%8,%9}, {%0,%1,%2,%3};"
        : "+f"(c[0]), "+f"(c[1]), "+f"(c[2]), "+f"(c[3])
        : "r"(a[0]), "r"(a[1]), "r"(a[2]), "r"(a[3]), "r"(b[0]), "r"(b[1]));
}

#define GK 16  // K chunk

__global__ __launch_bounds__(256) void k_gemm_tc(const float* __restrict__ A,
                                                 const float* __restrict__ W,
                                                 const float* __restrict__ b,
                                                 float* __restrict__ C) {
    // padded strides picked for conflict-free fragment LDS (136%32=8, 20 -> g*20+t4 unique)
    __shared__ float sWh[GK][136], sWl[GK][136];
    __shared__ float sAh[128][20], sAl[128][20];
    int tid  = threadIdx.x;          // 256
    int w    = tid >> 5;             // warp 0..7: owns n-slice [w*16, w*16+16)
    int lane = tid & 31;
    int g    = lane >> 2;            // 0..7
    int t4   = lane & 3;             // 0..3
    int rowbase = blockIdx.x * 128;
    int n0 = w * 16;

    float acc[8][2][4];
#pragma unroll
    for (int mt = 0; mt < 8; mt++)
#pragma unroll
        for (int nt = 0; nt < 2; nt++)
#pragma unroll
            for (int i = 0; i < 4; i++) acc[mt][nt][i] = 0.f;

    for (int kc = 0; kc < D; kc += GK) {
        // stage W chunk [GK x 128] as tf32 hi/lo: 512 float4, 2 per thread
#pragma unroll
        for (int i = tid; i < 512; i += 256) {
            int r = i >> 5, c4 = i & 31;
            float4 wv = ((const float4*)(W + (kc + r) * D))[c4];
            float4 hi, lo;
            hi.x = __uint_as_float(f2tf32(wv.x)); lo.x = __uint_as_float(f2tf32(wv.x - hi.x));
            hi.y = __uint_as_float(f2tf32(wv.y)); lo.y = __uint_as_float(f2tf32(wv.y - hi.y));
            hi.z = __uint_as_float(f2tf32(wv.z)); lo.z = __uint_as_float(f2tf32(wv.z - hi.z));
            hi.w = __uint_as_float(f2tf32(wv.w)); lo.w = __uint_as_float(f2tf32(wv.w - hi.w));
            *(float4*)&sWh[r][c4 * 4] = hi;
            *(float4*)&sWl[r][c4 * 4] = lo;
        }
        // stage A chunk [128 x GK] as tf32 hi/lo: 512 float4, 2 per thread
#pragma unroll
        for (int i = tid; i < 512; i += 256) {
            int r = i >> 2, c4 = i & 3;
            int gr = rowbase + r;
            float4 av = (gr < NN) ? ((const float4*)(A + gr * D + kc))[c4]
                                  : make_float4(0.f, 0.f, 0.f, 0.f);
            float4 hi, lo;
            hi.x = __uint_as_float(f2tf32(av.x)); lo.x = __uint_as_float(f2tf32(av.x - hi.x));
            hi.y = __uint_as_float(f2tf32(av.y)); lo.y = __uint_as_float(f2tf32(av.y - hi.y));
            hi.z = __uint_as_float(f2tf32(av.z)); lo.z = __uint_as_float(f2tf32(av.z - hi.z));
            hi.w = __uint_as_float(f2tf32(av.w)); lo.w = __uint_as_float(f2tf32(av.w - hi.w));
            *(float4*)&sAh[r][c4 * 4] = hi;
            *(float4*)&sAl[r][c4 * 4] = lo;
        }
        __syncthreads();

#pragma unroll
        for (int kt = 0; kt < GK / 8; kt++) {
            int k8 = kt * 8;
            // B fragments for this warp's two n-tiles (hoisted across all m-tiles)
            uint32_t bh[2][2], bl[2][2];
#pragma unroll
            for (int nt = 0; nt < 2; nt++) {
                int n = n0 + nt * 8 + g;
                bh[nt][0] = __float_as_uint(sWh[k8 + t4][n]);
                bh[nt][1] = __float_as_uint(sWh[k8 + t4 + 4][n]);
                bl[nt][0] = __float_as_uint(sWl[k8 + t4][n]);
                bl[nt][1] = __float_as_uint(sWl[k8 + t4 + 4][n]);
            }
#pragma unroll
            for (int mt = 0; mt < 8; mt++) {
                int r0 = mt * 16 + g;
                uint32_t ah[4], al[4];
                ah[0] = __float_as_uint(sAh[r0][k8 + t4]);
                ah[1] = __float_as_uint(sAh[r0 + 8][k8 + t4]);
                ah[2] = __float_as_uint(sAh[r0][k8 + t4 + 4]);
                ah[3] = __float_as_uint(sAh[r0 + 8][k8 + t4 + 4]);
                al[0] = __float_as_uint(sAl[r0][k8 + t4]);
                al[1] = __float_as_uint(sAl[r0 + 8][k8 + t4]);
                al[2] = __float_as_uint(sAl[r0][k8 + t4 + 4]);
                al[3] = __float_as_uint(sAl[r0 + 8][k8 + t4 + 4]);
#pragma unroll
                for (int nt = 0; nt < 2; nt++) {
                    mma_tf32(acc[mt][nt], al, bh[nt]);  // small terms first
                    mma_tf32(acc[mt][nt], ah, bl[nt]);
                    mma_tf32(acc[mt][nt], ah, bh[nt]);
                }
            }
        }
        __syncthreads();
    }

    // epilogue: bias + store (c0,c1 at row, c2,c3 at row+8; n = n0+nt*8+t4*2)
#pragma unroll
    for (int mt = 0; mt < 8; mt++) {
#pragma unroll
        for (int nt = 0; nt < 2; nt++) {
            int n = n0 + nt * 8 + t4 * 2;
            float2 bb = *(const float2*)&b[n];
            int r = rowbase + mt * 16 + g;
            if (r < NN) {
                float2 o = make_float2(acc[mt][nt][0] + bb.x, acc[mt][nt][1] + bb.y);
                *(float2*)&C[r * D + n] = o;
            }
            int r2 = r + 8;
            if (r2 < NN) {
                float2 o = make_float2(acc[mt][nt][2] + bb.x, acc[mt][nt][3] + bb.y);
                *(float2*)&C[r2 * D + n] = o;
            }
        }
    }
}

// ---------------- GENConv aggregation: one block per node, one thread per channel ----
__global__ void k_agg(const float* __restrict__ We, const float* __restrict__ be) {
    int v = blockIdx.x;
    int c = threadIdx.x;
    int s = g_row[v], e = g_row[v + 1];
    float we_c = We[c], be_c = be[c];
    float m = -1e30f, den = 0.f, ws = 0.f;
    for (int i = s; i < e; i++) {
        int   sr = __ldg(&g_srcs[i]);
        float a  = __ldg(&g_attrs[i]);
        float hv = g_h[sr * D + c];
        float msg = fmaxf(hv + a * we_c + be_c, 0.f) + EPSV;
        float newm  = fmaxf(m, msg);
        float scale = __expf(m - newm);
        float ex    = __expf(msg - newm);
        den = den * scale + ex;
        ws  = ws  * scale + ex * msg;
        m = newm;
    }
    float hvv = g_h[v * D + c];
    float agg = (e > s) ? (ws / den) : 0.f;
    g_out[v * D + c] = agg + hvv;
}

// ---------------- output head: out = h @ Wo + bo, one warp per node ----------------
__global__ void k_head(const float* __restrict__ Wo, const float* __restrict__ bo,
                       float* __restrict__ out) {
    int gw   = (blockIdx.x * blockDim.x + threadIdx.x) >> 5;
    int lane = threadIdx.x & 31;
    if (gw >= NN) return;
    float h0 = g_h[gw * D + lane];
    float h1 = g_h[gw * D + lane + 32];
    float h2 = g_h[gw * D + lane + 64];
    float h3 = g_h[gw * D + lane + 96];
#pragma unroll
    for (int o = 0; o < 3; o++) {
        float acc = h0 * __ldg(&Wo[lane * 3 + o]) + h1 * __ldg(&Wo[(lane + 32) * 3 + o]) +
                    h2 * __ldg(&Wo[(lane + 64) * 3 + o]) + h3 * __ldg(&Wo[(lane + 96) * 3 + o]);
#pragma unroll
        for (int off = 16; off; off >>= 1) acc += __shfl_down_sync(0xffffffff, acc, off);
        if (lane == 0) out[gw * 3 + o] = acc + bo[o];
    }
}

// ---------------- launch ----------------
extern "C" void kernel_launch(void* const* d_in, const int* in_sizes, int n_in,
                              void* d_out, int out_size) {
    const float* x    = (const float*)d_in[0];
    const int*   ei   = (const int*)d_in[1];   // [2, NE]
    const float* attr = (const float*)d_in[2];
    const float* Wn1  = (const float*)d_in[3];
    const float* bn1  = (const float*)d_in[4];
    const float* Wn2  = (const float*)d_in[5];
    const float* bn2  = (const float*)d_in[6];
    const float* We   = (const float*)d_in[7];
    const float* be   = (const float*)d_in[8];
    const float* Wg   = (const float*)d_in[9];  // [4,128,128]
    const float* bg   = (const float*)d_in[10]; // [4,128]
    const float* Wo   = (const float*)d_in[11];
    const float* bo   = (const float*)d_in[12];
    float* out = (float*)d_out;

    const int* src = ei;
    const int* dst = ei + NE;

    float* p_h;
    float* p_out;
    cudaGetSymbolAddress((void**)&p_h, g_h);
    cudaGetSymbolAddress((void**)&p_out, g_out);

    // ---- CSR build (deterministic after per-node sort) ----
    k_zero<<<(NN + 255) / 256, 256>>>();
    k_hist<<<(NE + 255) / 256, 256>>>(dst);
    k_scan<<<1, 1024>>>();
    k_scatter<<<(NE + 255) / 256, 256>>>(src, dst, attr);
    k_sort<<<(NN + 255) / 256, 256>>>();

    // ---- node encoder ----
    k_enc1<<<NN, D>>>(x, Wn1, bn1);                    // g_out = relu(x@Wn1+bn1)
    int gblocks = (NN + 127) / 128;
    k_gemm_tc<<<gblocks, 256>>>(p_out, Wn2, bn2, p_h); // g_h = g_out@Wn2+bn2

    // ---- 4 GENConv layers ----
    for (int l = 0; l < NL; l++) {
        k_agg<<<NN, D>>>(We, be);                                        // g_out = agg + g_h
        k_gemm_tc<<<gblocks, 256>>>(p_out, Wg + l * D * D, bg + l * D, p_h);
    }

    // ---- head ----
    k_head<<<(NN * 32 + 255) / 256, 256>>>(Wo, bo, out);
}

// round 5
// speedup vs baseline: 1.1213x; 1.0887x over previous
#include <cuda_runtime.h>
#include <math.h>
#include <stdint.h>

#define D   128
#define NN  30000
#define NE  480000
#define NL  4
#define EPSV 1e-7f

// ---------------- device scratch (static, no allocation) ----------------
__device__ float g_h[NN * D];     // current node features
__device__ float g_out[NN * D];   // post-aggregation (agg + residual)
__device__ int   g_srcs[NE];      // CSR-ordered source node per edge
__device__ float g_attrs[NE];     // CSR-ordered edge attr scalar per edge
__device__ int   g_eids[NE];      // CSR-ordered original edge ids (determinism sort key)
__device__ int   g_row[NN + 1];   // CSR row offsets
__device__ int   g_cur[NN];       // histogram / scatter cursor

// ---------------- CSR build ----------------
__global__ void k_zero() {
    int i = blockIdx.x * blockDim.x + threadIdx.x;
    if (i < NN) g_cur[i] = 0;
}

__global__ void k_hist(const int* __restrict__ dst) {
    int e = blockIdx.x * blockDim.x + threadIdx.x;
    if (e < NE) atomicAdd(&g_cur[dst[e]], 1);
}

// single-block exclusive scan of g_cur -> g_row, also reset g_cur to row start (cursor)
__global__ void k_scan() {
    __shared__ int ssum[1024];
    int t = threadIdx.x;
    const int CH = (NN + 1023) / 1024;  // 30
    int base = t * CH;
    int s = 0;
    for (int i = 0; i < CH; i++) {
        int idx = base + i;
        if (idx < NN) s += g_cur[idx];
    }
    ssum[t] = s;
    __syncthreads();
    for (int off = 1; off < 1024; off <<= 1) {
        int v = (t >= off) ? ssum[t - off] : 0;
        __syncthreads();
        ssum[t] += v;
        __syncthreads();
    }
    int run = (t == 0) ? 0 : ssum[t - 1];
    for (int i = 0; i < CH; i++) {
        int idx = base + i;
        if (idx < NN) {
            int c = g_cur[idx];
            g_row[idx] = run;
            g_cur[idx] = run;
            run += c;
        }
    }
    if (t == 1023) g_row[NN] = run;
}

__global__ void k_scatter(const int* __restrict__ src, const int* __restrict__ dst,
                          const float* __restrict__ attr) {
    int e = blockIdx.x * blockDim.x + threadIdx.x;
    if (e >= NE) return;
    int d = dst[e];
    int pos = atomicAdd(&g_cur[d], 1);
    g_eids[pos]  = e;
    g_srcs[pos]  = src[e];
    g_attrs[pos] = attr[e];
}

// per-node insertion sort by edge id -> deterministic reduction order
__global__ void k_sort() {
    int v = blockIdx.x * blockDim.x + threadIdx.x;
    if (v >= NN) return;
    int s = g_row[v], e = g_row[v + 1];
    for (int i = s + 1; i < e; i++) {
        int   key = g_eids[i];
        int   sr  = g_srcs[i];
        float at  = g_attrs[i];
        int j = i - 1;
        while (j >= s && g_eids[j] > key) {
            g_eids[j + 1]  = g_eids[j];
            g_srcs[j + 1]  = g_srcs[j];
            g_attrs[j + 1] = g_attrs[j];
            j--;
        }
        g_eids[j + 1]  = key;
        g_srcs[j + 1]  = sr;
        g_attrs[j + 1] = at;
    }
}

// ---------------- node encoder stage 1: h1 = relu(x @ Wn1 + bn1) ----------------
__global__ void k_enc1(const float* __restrict__ x, const float* __restrict__ Wn1,
                       const float* __restrict__ bn1) {
    int v = blockIdx.x;
    int c = threadIdx.x;
    __shared__ float sx[7];
    if (c < 7) sx[c] = x[v * 7 + c];
    __syncthreads();
    float acc = bn1[c];
#pragma unroll
    for (int k = 0; k < 7; k++) acc += sx[k] * Wn1[k * D + c];
    g_out[v * D + c] = fmaxf(acc, 0.f);
}

// ---------------- tensor-core 128x128 Linear (3xTF32): C = A @ W + b ----------------
__device__ __forceinline__ uint32_t f2tf32(float x) {
    uint32_t r;
    asm("cvt.rna.tf32.f32 %0, %1;" : "=r"(r) : "f"(x));
    return r;
}
__device__ __forceinline__ void mma_tf32(float* c, const uint32_t* a, const uint32_t* b) {
    asm volatile(
        "mma.sync.aligned.m16n8k8.row.col.f32.tf32.tf32.f32 "
        "{%0,%1,%2,%3}, {%4,%5,%6,%7}, {%8,%9}, {%0,%1,%2,%3};"
        : "+f"(c[0]), "+f"(c[1]), "+f"(c[2]), "+f"(c[3])
        : "r"(a[0]), "r"(a[1]), "r"(a[2]), "r"(a[3]), "r"(b[0]), "r"(b[1]));
}

#define GK 16  // K chunk

__global__ __launch_bounds__(256) void k_gemm_tc(const float* __restrict__ A,
                                                 const float* __restrict__ W,
                                                 const float* __restrict__ b,
                                                 float* __restrict__ C) {
    // padded strides picked for conflict-free fragment LDS (136%32=8, 20 -> g*20+t4 unique)
    __shared__ float sWh[GK][136], sWl[GK][136];
    __shared__ float sAh[128][20], sAl[128][20];
    int tid  = threadIdx.x;          // 256
    int w    = tid >> 5;             // warp 0..7: owns n-slice [w*16, w*16+16)
    int lane = tid & 31;
    int g    = lane >> 2;            // 0..7
    int t4   = lane & 3;             // 0..3
    int rowbase = blockIdx.x * 128;
    int n0 = w * 16;

    float acc[8][2][4];
#pragma unroll
    for (int mt = 0; mt < 8; mt++)
#pragma unroll
        for (int nt = 0; nt < 2; nt++)
#pragma unroll
            for (int i = 0; i < 4; i++) acc[mt][nt][i] = 0.f;

    for (int kc = 0; kc < D; kc += GK) {
        // stage W chunk [GK x 128] as tf32 hi/lo: 512 float4, 2 per thread
#pragma unroll
        for (int i = tid; i < 512; i += 256) {
            int r = i >> 5, c4 = i & 31;
            float4 wv = ((const float4*)(W + (kc + r) * D))[c4];
            float4 hi, lo;
            hi.x = __uint_as_float(f2tf32(wv.x)); lo.x = __uint_as_float(f2tf32(wv.x - hi.x));
            hi.y = __uint_as_float(f2tf32(wv.y)); lo.y = __uint_as_float(f2tf32(wv.y - hi.y));
            hi.z = __uint_as_float(f2tf32(wv.z)); lo.z = __uint_as_float(f2tf32(wv.z - hi.z));
            hi.w = __uint_as_float(f2tf32(wv.w)); lo.w = __uint_as_float(f2tf32(wv.w - hi.w));
            *(float4*)&sWh[r][c4 * 4] = hi;
            *(float4*)&sWl[r][c4 * 4] = lo;
        }
        // stage A chunk [128 x GK] as tf32 hi/lo: 512 float4, 2 per thread
#pragma unroll
        for (int i = tid; i < 512; i += 256) {
            int r = i >> 2, c4 = i & 3;
            int gr = rowbase + r;
            float4 av = (gr < NN) ? ((const float4*)(A + gr * D + kc))[c4]
                                  : make_float4(0.f, 0.f, 0.f, 0.f);
            float4 hi, lo;
            hi.x = __uint_as_float(f2tf32(av.x)); lo.x = __uint_as_float(f2tf32(av.x - hi.x));
            hi.y = __uint_as_float(f2tf32(av.y)); lo.y = __uint_as_float(f2tf32(av.y - hi.y));
            hi.z = __uint_as_float(f2tf32(av.z)); lo.z = __uint_as_float(f2tf32(av.z - hi.z));
            hi.w = __uint_as_float(f2tf32(av.w)); lo.w = __uint_as_float(f2tf32(av.w - hi.w));
            *(float4*)&sAh[r][c4 * 4] = hi;
            *(float4*)&sAl[r][c4 * 4] = lo;
        }
        __syncthreads();

#pragma unroll
        for (int kt = 0; kt < GK / 8; kt++) {
            int k8 = kt * 8;
            uint32_t bh[2][2], bl[2][2];
#pragma unroll
            for (int nt = 0; nt < 2; nt++) {
                int n = n0 + nt * 8 + g;
                bh[nt][0] = __float_as_uint(sWh[k8 + t4][n]);
                bh[nt][1] = __float_as_uint(sWh[k8 + t4 + 4][n]);
                bl[nt][0] = __float_as_uint(sWl[k8 + t4][n]);
                bl[nt][1] = __float_as_uint(sWl[k8 + t4 + 4][n]);
            }
#pragma unroll
            for (int mt = 0; mt < 8; mt++) {
                int r0 = mt * 16 + g;
                uint32_t ah[4], al[4];
                ah[0] = __float_as_uint(sAh[r0][k8 + t4]);
                ah[1] = __float_as_uint(sAh[r0 + 8][k8 + t4]);
                ah[2] = __float_as_uint(sAh[r0][k8 + t4 + 4]);
                ah[3] = __float_as_uint(sAh[r0 + 8][k8 + t4 + 4]);
                al[0] = __float_as_uint(sAl[r0][k8 + t4]);
                al[1] = __float_as_uint(sAl[r0 + 8][k8 + t4]);
                al[2] = __float_as_uint(sAl[r0][k8 + t4 + 4]);
                al[3] = __float_as_uint(sAl[r0 + 8][k8 + t4 + 4]);
#pragma unroll
                for (int nt = 0; nt < 2; nt++) {
                    mma_tf32(acc[mt][nt], al, bh[nt]);  // small terms first
                    mma_tf32(acc[mt][nt], ah, bl[nt]);
                    mma_tf32(acc[mt][nt], ah, bh[nt]);
                }
            }
        }
        __syncthreads();
    }

#pragma unroll
    for (int mt = 0; mt < 8; mt++) {
#pragma unroll
        for (int nt = 0; nt < 2; nt++) {
            int n = n0 + nt * 8 + t4 * 2;
            float2 bb = *(const float2*)&b[n];
            int r = rowbase + mt * 16 + g;
            if (r < NN) {
                float2 o = make_float2(acc[mt][nt][0] + bb.x, acc[mt][nt][1] + bb.y);
                *(float2*)&C[r * D + n] = o;
            }
            int r2 = r + 8;
            if (r2 < NN) {
                float2 o = make_float2(acc[mt][nt][2] + bb.x, acc[mt][nt][3] + bb.y);
                *(float2*)&C[r2 * D + n] = o;
            }
        }
    }
}

// ---------------- GENConv aggregation ----------------
// One block (128 threads) per node, one thread per channel.
// Edge list staged in smem; online softmax with a SINGLE exp per edge:
//   only one of {exp(m-newm), exp(msg-newm)} is != 1, so compute t=exp(-|msg-m|)
//   and select which accumulator it scales.
__global__ void k_agg(const float* __restrict__ We, const float* __restrict__ be) {
    int v = blockIdx.x;
    int c = threadIdx.x;
    __shared__ int   s_src[128];
    __shared__ float s_attr[128];
    int s = g_row[v], e = g_row[v + 1];
    float we_c = We[c], be_c = be[c];
    float m = -1e30f, den = 0.f, ws = 0.f;
    for (int base = s; base < e; base += 128) {
        int n = min(128, e - base);
        if (c < n) {
            s_src[c]  = g_srcs[base + c];
            s_attr[c] = g_attrs[base + c];
        }
        __syncthreads();
        for (int i = 0; i < n; i++) {
            float hv  = g_h[s_src[i] * D + c];
            float msg = fmaxf(hv + s_attr[i] * we_c + be_c, 0.f) + EPSV;
            float d   = msg - m;
            float t   = __expf(-fabsf(d));  // exp(min-max), the only nontrivial factor
            bool  up  = d > 0.f;
            float nden = up ? den * t + 1.f : den + t;
            float nws  = up ? ws  * t + msg : ws + t * msg;
            m   = up ? msg : m;
            den = nden;
            ws  = nws;
        }
        __syncthreads();
    }
    float agg = (e > s) ? (ws / den) : 0.f;
    g_out[v * D + c] = agg + g_h[v * D + c];
}

// ---------------- output head: out = h @ Wo + bo, one warp per node ----------------
__global__ void k_head(const float* __restrict__ Wo, const float* __restrict__ bo,
                       float* __restrict__ out) {
    int gw   = (blockIdx.x * blockDim.x + threadIdx.x) >> 5;
    int lane = threadIdx.x & 31;
    if (gw >= NN) return;
    float h0 = g_h[gw * D + lane];
    float h1 = g_h[gw * D + lane + 32];
    float h2 = g_h[gw * D + lane + 64];
    float h3 = g_h[gw * D + lane + 96];
#pragma unroll
    for (int o = 0; o < 3; o++) {
        float acc = h0 * __ldg(&Wo[lane * 3 + o]) + h1 * __ldg(&Wo[(lane + 32) * 3 + o]) +
                    h2 * __ldg(&Wo[(lane + 64) * 3 + o]) + h3 * __ldg(&Wo[(lane + 96) * 3 + o]);
#pragma unroll
        for (int off = 16; off; off >>= 1) acc += __shfl_down_sync(0xffffffff, acc, off);
        if (lane == 0) out[gw * 3 + o] = acc + bo[o];
    }
}

// ---------------- launch ----------------
// Launch order puts the first k_gemm_tc at our launch index 3 (the slot ncu
// profiles) so next round's profile finally shows GEMM instead of k_scatter.
// Stream order still satisfies all data dependencies.
extern "C" void kernel_launch(void* const* d_in, const int* in_sizes, int n_in,
                              void* d_out, int out_size) {
    const float* x    = (const float*)d_in[0];
    const int*   ei   = (const int*)d_in[1];   // [2, NE]
    const float* attr = (const float*)d_in[2];
    const float* Wn1  = (const float*)d_in[3];
    const float* bn1  = (const float*)d_in[4];
    const float* Wn2  = (const float*)d_in[5];
    const float* bn2  = (const float*)d_in[6];
    const float* We   = (const float*)d_in[7];
    const float* be   = (const float*)d_in[8];
    const float* Wg   = (const float*)d_in[9];  // [4,128,128]
    const float* bg   = (const float*)d_in[10]; // [4,128]
    const float* Wo   = (const float*)d_in[11];
    const float* bo   = (const float*)d_in[12];
    float* out = (float*)d_out;

    const int* src = ei;
    const int* dst = ei + NE;

    float* p_h;
    float* p_out;
    cudaGetSymbolAddress((void**)&p_h, g_h);
    cudaGetSymbolAddress((void**)&p_out, g_out);

    int gblocks = (NN + 127) / 128;

    // idx 0: encoder stage 1 (independent of CSR)
    k_enc1<<<NN, D>>>(x, Wn1, bn1);                    // g_out = relu(x@Wn1+bn1)
    // idx 1-2: CSR build start
    k_zero<<<(NN + 255) / 256, 256>>>();
    k_hist<<<(NE + 255) / 256, 256>>>(dst);
    // idx 3: encoder GEMM  <-- profiled slot
    k_gemm_tc<<<gblocks, 256>>>(p_out, Wn2, bn2, p_h); // g_h = g_out@Wn2+bn2
    // idx 4-6: CSR build finish
    k_scan<<<1, 1024>>>();
    k_scatter<<<(NE + 255) / 256, 256>>>(src, dst, attr);
    k_sort<<<(NN + 255) / 256, 256>>>();

    // ---- 4 GENConv layers ----
    for (int l = 0; l < NL; l++) {
        k_agg<<<NN, D>>>(We, be);                                        // g_out = agg + g_h
        k_gemm_tc<<<gblocks, 256>>>(p_out, Wg + l * D * D, bg + l * D, p_h);
    }

    // ---- head ----
    k_head<<<(NN * 32 + 255) / 256, 256>>>(Wo, bo, out);
}